// round 16
// baseline (speedup 1.0000x reference)
#include <cuda_runtime.h>
#include <cuda_fp16.h>
#include <cstdint>

#define Bb 8
#define Cc 128
#define Nn 10000
#define Kk 16
#define CO 256
#define NT (Bb*Nn)
#define S1 136              // k1 padded smem stride (halves) -> 272B rows
#define SK 72               // k2 B/G stage stride (64 + 8 pad) -> 144B rows
#define SA 264              // k2 A stride (256 + 8 pad) -> 528B rows
#define NTILE 625
#define GRID2 148

// ---------------------------------------------------------------------------
// Device scratch (all fp16)
// ---------------------------------------------------------------------------
__device__ __align__(16) __half g_w1h[16384];
__device__ __align__(16) __half g_wph[16384];
__device__ __align__(16) __half g_w2h[65536];
__device__ __align__(16) __half g_cat[(size_t)NT*128];        // h, fp16
__device__ __align__(16) __half g_q[(size_t)NT*128];          // q, fp16

// D(16x8,f32) += A(16x16,fp16 row) * B(16x8,fp16 col)
__device__ __forceinline__ void mma_f16(float* d, const uint32_t* a, const uint32_t* b) {
    asm("mma.sync.aligned.m16n8k16.row.col.f32.f16.f16.f32 "
        "{%0,%1,%2,%3}, {%4,%5,%6,%7}, {%8,%9}, {%0,%1,%2,%3};"
        : "+f"(d[0]), "+f"(d[1]), "+f"(d[2]), "+f"(d[3])
        : "r"(a[0]), "r"(a[1]), "r"(a[2]), "r"(a[3]), "r"(b[0]), "r"(b[1]));
}

__device__ __forceinline__ void ldm4(uint32_t r[4], uint32_t addr) {
    asm volatile("ldmatrix.sync.aligned.m8n8.x4.shared.b16 {%0,%1,%2,%3}, [%4];"
        : "=r"(r[0]), "=r"(r[1]), "=r"(r[2]), "=r"(r[3]) : "r"(addr));
}

__device__ __forceinline__ uint32_t s2u(const void* p) {
    uint32_t a;
    asm("{ .reg .u64 t; cvta.to.shared.u64 t, %1; cvt.u32.u64 %0, t; }" : "=r"(a) : "l"(p));
    return a;
}
__device__ __forceinline__ void cp16(uint32_t dst, const void* src) {
    asm volatile("cp.async.cg.shared.global [%0], [%1], 16;" :: "r"(dst), "l"(src));
}
#define CP_COMMIT() asm volatile("cp.async.commit_group;" ::: "memory")
#define CP_WAIT(N)  asm volatile("cp.async.wait_group %0;" :: "n"(N) : "memory")

// Warp GEMM, tile 32(M) x 32(N), K=128, single-term fp16, ldmatrix frags (k1).
__device__ __forceinline__ void gemm_f16_2x4(float acc[2][4][4],
        uint32_t aA, uint32_t aB, int m0, int n0, int lane)
{
    const int rowA = lane & 15, khalf = (lane >> 4) * 8;
    #pragma unroll
    for (int kk = 0; kk < 8; kk++) {
        const int k0 = kk * 16;
        uint32_t a[2][4];
        #pragma unroll
        for (int mi = 0; mi < 2; mi++)
            ldm4(a[mi], aA + (uint32_t)(((m0 + mi*16 + rowA) * S1 + k0 + khalf) * 2));
        #pragma unroll
        for (int np = 0; np < 2; np++) {
            uint32_t bm[4];
            ldm4(bm, aB + (uint32_t)(((n0 + np*16 + rowA) * S1 + k0 + khalf) * 2));
            uint32_t b0[2] = {bm[0], bm[2]}, b1[2] = {bm[1], bm[3]};
            #pragma unroll
            for (int mi = 0; mi < 2; mi++) {
                mma_f16(acc[mi][2*np],   a[mi], b0);
                mma_f16(acc[mi][2*np+1], a[mi], b1);
            }
        }
    }
}

// ---------------------------------------------------------------------------
// kw: one-time fp16 conversion of W1 + Wp ONLY (W2 converted in k1 tail)
// ---------------------------------------------------------------------------
__global__ void kw(const float* __restrict__ W1, const float* __restrict__ Wp) {
    int t = blockIdx.x * 256 + threadIdx.x;     // 32768
    if (t < 16384) g_w1h[t] = __float2half_rn(W1[t]);
    else           g_wph[t - 16384] = __float2half_rn(Wp[t - 16384]);
}

// ---------------------------------------------------------------------------
// k1: per 128-node tile: h = relu(W1@x+b1); q = relu(Wp@h+bp)
//     h -> g_cat, q -> g_q. 512 threads, 2 CTAs/SM. Blocks 0-63 also convert
//     W2 fp32 -> g_w2h at the end (k2 depends on k1 completion anyway).
// ---------------------------------------------------------------------------
__global__ __launch_bounds__(512, 2)
void k1(const float* __restrict__ x, const float* __restrict__ b1v,
        const float* __restrict__ bpv, const float* __restrict__ W2f)
{
    extern __shared__ unsigned char sm[];
    const uint32_t sbu = s2u(sm);
    int* xb = (int*)sm;
    __half* Bf = (__half*)(sm + 512 + 2*34816);
    __half* Qh = (__half*)(sm + 512);     // overlay W1 plane after GEMM1
    const uint32_t aW1 = sbu + 512, aWp = aW1 + 34816, aB = aWp + 34816;

    const int tid = threadIdx.x, lane = tid & 31, wid = tid >> 5;
    const int r = lane >> 2, c = (lane & 3) * 2;
    const int m0 = (wid >> 2) * 32, n0 = (wid & 3) * 32;
    const int col0 = blockIdx.x * 128;

    // W1 + Wp -> smem via cp.async, in flight during x transpose
    #pragma unroll
    for (int t = 0; t < 4; t++) {
        int i = tid + t * 512;            // 0..2047
        int m = i >> 4, ch = i & 15;
        uint32_t doff = (uint32_t)(m * 272 + ch * 16);
        cp16(aW1 + doff, g_w1h + m * 128 + ch * 8);
        cp16(aWp + doff, g_wph + m * 128 + ch * 8);
    }
    CP_COMMIT();

    if (tid < 128) {
        int col = col0 + tid, b = col / Nn;
        xb[tid] = b * (Cc * Nn) + (col - b * Nn);
    }
    __syncthreads();

    for (int i = tid; i < 16384; i += 512) {
        int j = i & 127, ch = i >> 7;
        Bf[j*S1 + ch] = __float2half_rn(x[xb[j] + ch * Nn]);
    }
    CP_WAIT(0);
    __syncthreads();

    float acc[2][4][4];
    #pragma unroll
    for (int i = 0; i < 2; i++)
        #pragma unroll
        for (int j = 0; j < 4; j++)
            #pragma unroll
            for (int v = 0; v < 4; v++) acc[i][j][v] = 0.f;

    gemm_f16_2x4(acc, aW1, aB, m0, n0, lane);
    __syncthreads();

    // Epilogue 1: h -> B plane in place
    #pragma unroll
    for (int mi = 0; mi < 2; mi++) {
        int mr = m0 + mi*16 + r;
        float bias_a = b1v[mr], bias_b = b1v[mr + 8];
        #pragma unroll
        for (int ni = 0; ni < 4; ni++) {
            int nc = n0 + ni*8 + c;
            Bf[nc*S1 + mr]       = __float2half_rn(fmaxf(acc[mi][ni][0] + bias_a, 0.f));
            Bf[(nc+1)*S1 + mr]   = __float2half_rn(fmaxf(acc[mi][ni][1] + bias_a, 0.f));
            Bf[nc*S1 + mr+8]     = __float2half_rn(fmaxf(acc[mi][ni][2] + bias_b, 0.f));
            Bf[(nc+1)*S1 + mr+8] = __float2half_rn(fmaxf(acc[mi][ni][3] + bias_b, 0.f));
        }
    }
    __syncthreads();

    for (int i = tid; i < 2048; i += 512) {
        int j = i >> 4, v = i & 15;
        ((uint4*)(g_cat + (size_t)(col0 + j) * 128))[v] = ((const uint4*)(Bf + j*S1))[v];
    }

    #pragma unroll
    for (int i = 0; i < 2; i++)
        #pragma unroll
        for (int j = 0; j < 4; j++)
            #pragma unroll
            for (int v = 0; v < 4; v++) acc[i][j][v] = 0.f;

    gemm_f16_2x4(acc, aWp, aB, m0, n0, lane);
    // no sync: epilogue 2 writes the W1 plane, never read by GEMM2

    #pragma unroll
    for (int mi = 0; mi < 2; mi++) {
        int mr = m0 + mi*16 + r;
        float bias_a = bpv[mr], bias_b = bpv[mr + 8];
        #pragma unroll
        for (int ni = 0; ni < 4; ni++) {
            int nc = n0 + ni*8 + c;
            Qh[nc*S1 + mr]       = __float2half_rn(fmaxf(acc[mi][ni][0] + bias_a, 0.f));
            Qh[(nc+1)*S1 + mr]   = __float2half_rn(fmaxf(acc[mi][ni][1] + bias_a, 0.f));
            Qh[nc*S1 + mr+8]     = __float2half_rn(fmaxf(acc[mi][ni][2] + bias_b, 0.f));
            Qh[(nc+1)*S1 + mr+8] = __float2half_rn(fmaxf(acc[mi][ni][3] + bias_b, 0.f));
        }
    }
    __syncthreads();

    for (int i = tid; i < 2048; i += 512) {
        int j = i >> 4, v = i & 15;
        ((uint4*)(g_q + (size_t)(col0 + j) * 128))[v] = ((const uint4*)(Qh + j*S1))[v];
    }

    // Tail: blocks 0-63 convert W2 fp32 -> fp16 (2 elems/thread, 65536 total)
    if (blockIdx.x < 64) {
        int e = (blockIdx.x << 10) + (tid << 1);
        float2 w = *(const float2*)(W2f + e);
        __half2 p = __floats2half2_rn(w.x, w.y);
        *(__half2*)(g_w2h + e) = p;
    }
}

// ---------------------------------------------------------------------------
// k2: PERSISTENT + WARP-SPECIALIZED. out = relu(W2 @ cat + b2), fp16 MMA.
// grid 148, 512 thr. W2 resident in smem (A plane). Warps 0-7 = MMA consumers
// (256x128 tile, two M-halves of 128, warp tile 32x64). Warps 8-15 = gather
// producers: gather-max for tile t+1 into regs WHILE consumers MMA tile t.
// smem: [A 135168][B0 18432][B1 18432][G2 18432][G3 18432] = 208896
// ---------------------------------------------------------------------------
#define K2_A  0
#define K2_B0 135168
#define K2_B1 153600
#define K2_G2 172032
#define K2_G3 190464

__device__ __forceinline__ void k2_load_b(uint32_t sbu, int col0, int tid) {
    // B0 (h ch 0-63) + B1 (h ch 64-127): 2048 cp16, 4 per thread
    #pragma unroll
    for (int t = 0; t < 2; t++) {
        int i = tid + t * 512;           // 0..1023
        int j = i >> 3, ch = i & 7;
        uint32_t doff = (uint32_t)(j * SK + ch * 8) * 2;
        cp16(sbu + K2_B0 + doff, g_cat + (size_t)(col0 + j) * 128 + ch * 8);
        cp16(sbu + K2_B1 + doff, g_cat + (size_t)(col0 + j) * 128 + 64 + ch * 8);
    }
}

// gather-max one node-set: node j = jb + js*t for t in [0,nt); lane ch=lane*4
template<int NTT>
__device__ __forceinline__ void k2_gather_t(const int* __restrict__ eidx, int col0,
                                            int jb, int js, int lane, uint2* g) {
    #pragma unroll
    for (int t = 0; t < NTT; t++) {
        int col = col0 + jb + js * t;
        int b = col / Nn;
        const __half* qb = g_q + (size_t)b * Nn * 128;
        int id = 0;
        if (lane < Kk) id = eidx[col * Kk + lane];
        __half2 m0 = __half2{__half(0.f), __half(0.f)}, m1 = m0;   // q >= 0
        #pragma unroll
        for (int k = 0; k < Kk; k++) {
            int nb = __shfl_sync(0xffffffffu, id, k);
            uint2 v = *(const uint2*)(qb + (size_t)nb * 128 + lane * 4);
            m0 = __hmax2(m0, *(__half2*)&v.x);
            m1 = __hmax2(m1, *(__half2*)&v.y);
        }
        g[t] = make_uint2(*(uint32_t*)&m0, *(uint32_t*)&m1);
    }
}

// store gathered regs: lanes 0-15 -> G2 (q ch 0-63), lanes 16-31 -> G3
template<int NTT>
__device__ __forceinline__ void k2_store_g(unsigned char* sm, const uint2* g,
                                           int jb, int js, int lane) {
    unsigned char* G = sm + ((lane >> 4) ? K2_G3 : K2_G2);
    const int kloc = (lane & 15) * 4;
    #pragma unroll
    for (int t = 0; t < NTT; t++) {
        int j = jb + js * t;
        *(uint2*)(G + (j * SK + kloc) * 2) = g[t];
    }
}

// one K=64 chunk: A from resident plane (stride SA, aA includes chunk+mh offs),
// B from stage (stride SK). Warp tile 32x64.
__device__ __forceinline__ void k2_gemm_p(float acc[2][8][4], uint32_t aA,
                                          uint32_t aB, int m0, int n0, int lane) {
    const int rowA = lane & 15, khalf = (lane >> 4) * 8;
    #pragma unroll
    for (int kk = 0; kk < 4; kk++) {
        const int k0 = kk * 16;
        uint32_t a[2][4];
        #pragma unroll
        for (int mi = 0; mi < 2; mi++)
            ldm4(a[mi], aA + (uint32_t)(((m0 + mi*16 + rowA) * SA + k0 + khalf) * 2));
        #pragma unroll
        for (int np = 0; np < 4; np++) {
            uint32_t bm[4];
            ldm4(bm, aB + (uint32_t)(((n0 + np*16 + rowA) * SK + k0 + khalf) * 2));
            uint32_t b0[2] = {bm[0], bm[2]}, b1[2] = {bm[1], bm[3]};
            #pragma unroll
            for (int mi = 0; mi < 2; mi++) {
                mma_f16(acc[mi][2*np],   a[mi], b0);
                mma_f16(acc[mi][2*np+1], a[mi], b1);
            }
        }
    }
}

__global__ __launch_bounds__(512, 1)
void k2(const int* __restrict__ eidx, const float* __restrict__ b2v,
        float* __restrict__ out)
{
    extern __shared__ unsigned char sm[];
    const uint32_t sbu = s2u(sm);
    const int tid = threadIdx.x, lane = tid & 31, wid = tid >> 5;
    const int r = lane >> 2, c = (lane & 3) * 2;
    const bool producer = wid >= 8;
    const int pw = wid & 7;               // producer index / consumer index
    const int m0c = (pw >> 1) * 32, n0c = (pw & 1) * 64;   // consumer warp slot

    // ---- Prologue ----
    // A (full W2) -> resident smem plane
    #pragma unroll
    for (int t = 0; t < 16; t++) {
        int i = tid + t * 512;           // 0..8191
        int m = i >> 5, ch = i & 31;
        cp16(sbu + K2_A + (uint32_t)(m * SA + ch * 8) * 2, g_w2h + m * 256 + ch * 8);
    }
    int tile = blockIdx.x;
    int col0 = tile * 128;
    k2_load_b(sbu, col0, tid);
    CP_COMMIT();

    // tile0 gather by ALL 16 warps (8 rounds: node = wid + 16t)
    {
        uint2 g0[8];
        k2_gather_t<8>(eidx, col0, wid, 16, lane, g0);
        CP_WAIT(0);
        __syncthreads();
        k2_store_g<8>(sm, g0, wid, 16, lane);
        __syncthreads();
    }

    float acc[2][8][4];
    uint2 g[16];
    #pragma unroll
    for (int i = 0; i < 2; i++)
        #pragma unroll
        for (int j = 0; j < 8; j++)
            #pragma unroll
            for (int v = 0; v < 4; v++) acc[i][j][v] = 0.f;

    // ---- Persistent loop ----
    for (; tile < NTILE; tile += GRID2) {
        col0 = tile * 128;
        const int ntile = tile + GRID2;
        const bool has_next = ntile < NTILE;

        if (producer) {
            // gather tile t+1 into regs (16 rounds: node = pw + 8t)
            if (has_next)
                k2_gather_t<16>(eidx, ntile * 128, pw, 8, lane, g);
        } else {
            // consumers: two M-halves of 128 rows each
            #pragma unroll
            for (int mh = 0; mh < 2; mh++) {
                const uint32_t aAm = sbu + K2_A + (uint32_t)(mh * 128 * SA * 2);
                k2_gemm_p(acc, aAm + 0,   sbu + K2_B0, m0c, n0c, lane);
                k2_gemm_p(acc, aAm + 128, sbu + K2_B1, m0c, n0c, lane);
                k2_gemm_p(acc, aAm + 256, sbu + K2_G2, m0c, n0c, lane);
                k2_gemm_p(acc, aAm + 384, sbu + K2_G3, m0c, n0c, lane);

                // epilogue for this M-half
                #pragma unroll
                for (int mi = 0; mi < 2; mi++) {
                    int mr = mh * 128 + m0c + mi*16 + r;
                    float bias_a = b2v[mr], bias_b = b2v[mr + 8];
                    #pragma unroll
                    for (int ni = 0; ni < 8; ni++) {
                        int nc = n0c + ni*8 + c;
                        int colA = col0 + nc, colB = colA + 1;
                        int ba = colA / Nn, bb = colB / Nn;
                        size_t obA = (size_t)ba * CO * Nn + (colA - ba * Nn);
                        size_t obB = (size_t)bb * CO * Nn + (colB - bb * Nn);
                        out[obA + (size_t)mr * Nn]     = fmaxf(acc[mi][ni][0] + bias_a, 0.f);
                        out[obB + (size_t)mr * Nn]     = fmaxf(acc[mi][ni][1] + bias_a, 0.f);
                        out[obA + (size_t)(mr+8) * Nn] = fmaxf(acc[mi][ni][2] + bias_b, 0.f);
                        out[obB + (size_t)(mr+8) * Nn] = fmaxf(acc[mi][ni][3] + bias_b, 0.f);
                        acc[mi][ni][0] = acc[mi][ni][1] = acc[mi][ni][2] = acc[mi][ni][3] = 0.f;
                    }
                }
            }
        }
        __syncthreads();                 // stage reads done; gathers done

        if (has_next) {
            if (producer)
                k2_store_g<16>(sm, g, pw, 8, lane);
            k2_load_b(sbu, ntile * 128, tid);   // all threads issue cp.async
            CP_COMMIT();
            CP_WAIT(0);
            __syncthreads();             // B arrived; G stores visible
        }
    }
}

// ---------------------------------------------------------------------------
extern "C" void kernel_launch(void* const* d_in, const int* in_sizes, int n_in,
                              void* d_out, int out_size)
{
    const float* x  = (const float*)d_in[0];
    const int*   ei = (const int*)  d_in[1];
    const float* W1 = (const float*)d_in[2];
    const float* b1 = (const float*)d_in[3];
    const float* Wp = (const float*)d_in[4];
    const float* bp = (const float*)d_in[5];
    const float* W2 = (const float*)d_in[6];
    const float* b2 = (const float*)d_in[7];
    float* out = (float*)d_out;

    const int s1 = 512 + 3 * 34816;   // 104960
    const int s2 = 208896;
    cudaFuncSetAttribute(k1, cudaFuncAttributeMaxDynamicSharedMemorySize, s1);
    cudaFuncSetAttribute(k2, cudaFuncAttributeMaxDynamicSharedMemorySize, s2);

    kw<<<128, 256>>>(W1, Wp);
    k1<<<NT / 128, 512, s1>>>(x, b1, bp, W2);
    k2<<<GRID2, 512, s2>>>(ei, b2, out);
}

// round 17
// speedup vs baseline: 1.5244x; 1.5244x over previous
#include <cuda_runtime.h>
#include <cuda_fp16.h>
#include <cstdint>

#define Bb 8
#define Cc 128
#define Nn 10000
#define Kk 16
#define CO 256
#define NT (Bb*Nn)
#define S1 136              // k1 padded smem stride (halves) -> 272B rows
#define SK 72               // k2 chunk stride (64 k-elems + 8 pad) -> 144B rows

// ---------------------------------------------------------------------------
// Device scratch (all fp16)
// ---------------------------------------------------------------------------
__device__ __align__(16) __half g_w1h[16384];
__device__ __align__(16) __half g_wph[16384];
__device__ __align__(16) __half g_w2h[65536];
__device__ __align__(16) __half g_cat[(size_t)NT*128];        // h, fp16
__device__ __align__(16) __half g_q[(size_t)NT*128];          // q, fp16

// D(16x8,f32) += A(16x16,fp16 row) * B(16x8,fp16 col)
__device__ __forceinline__ void mma_f16(float* d, const uint32_t* a, const uint32_t* b) {
    asm("mma.sync.aligned.m16n8k16.row.col.f32.f16.f16.f32 "
        "{%0,%1,%2,%3}, {%4,%5,%6,%7}, {%8,%9}, {%0,%1,%2,%3};"
        : "+f"(d[0]), "+f"(d[1]), "+f"(d[2]), "+f"(d[3])
        : "r"(a[0]), "r"(a[1]), "r"(a[2]), "r"(a[3]), "r"(b[0]), "r"(b[1]));
}

__device__ __forceinline__ void ldm4(uint32_t r[4], uint32_t addr) {
    asm volatile("ldmatrix.sync.aligned.m8n8.x4.shared.b16 {%0,%1,%2,%3}, [%4];"
        : "=r"(r[0]), "=r"(r[1]), "=r"(r[2]), "=r"(r[3]) : "r"(addr));
}

__device__ __forceinline__ uint32_t s2u(const void* p) {
    uint32_t a;
    asm("{ .reg .u64 t; cvta.to.shared.u64 t, %1; cvt.u32.u64 %0, t; }" : "=r"(a) : "l"(p));
    return a;
}
__device__ __forceinline__ void cp16(uint32_t dst, const void* src) {
    asm volatile("cp.async.cg.shared.global [%0], [%1], 16;" :: "r"(dst), "l"(src));
}
#define CP_COMMIT() asm volatile("cp.async.commit_group;" ::: "memory")
#define CP_WAIT(N)  asm volatile("cp.async.wait_group %0;" :: "n"(N) : "memory")

// Warp GEMM, tile 32(M) x 32(N), K=128, single-term fp16, ldmatrix frags.
__device__ __forceinline__ void gemm_f16_2x4(float acc[2][4][4],
        uint32_t aA, uint32_t aB, int m0, int n0, int lane)
{
    const int rowA = lane & 15, khalf = (lane >> 4) * 8;
    #pragma unroll
    for (int kk = 0; kk < 8; kk++) {
        const int k0 = kk * 16;
        uint32_t a[2][4];
        #pragma unroll
        for (int mi = 0; mi < 2; mi++)
            ldm4(a[mi], aA + (uint32_t)(((m0 + mi*16 + rowA) * S1 + k0 + khalf) * 2));
        #pragma unroll
        for (int np = 0; np < 2; np++) {
            uint32_t bm[4];
            ldm4(bm, aB + (uint32_t)(((n0 + np*16 + rowA) * S1 + k0 + khalf) * 2));
            uint32_t b0[2] = {bm[0], bm[2]}, b1[2] = {bm[1], bm[3]};
            #pragma unroll
            for (int mi = 0; mi < 2; mi++) {
                mma_f16(acc[mi][2*np],   a[mi], b0);
                mma_f16(acc[mi][2*np+1], a[mi], b1);
            }
        }
    }
}

// ---------------------------------------------------------------------------
// kw: one-time fp16 conversion of all weights
// ---------------------------------------------------------------------------
__global__ void kw(const float* __restrict__ W1, const float* __restrict__ Wp,
                   const float* __restrict__ W2) {
    int t = blockIdx.x * 256 + threadIdx.x;     // 98304
    if (t < 16384)       g_w1h[t] = __float2half_rn(W1[t]);
    else if (t < 32768)  g_wph[t - 16384] = __float2half_rn(Wp[t - 16384]);
    else                 g_w2h[t - 32768] = __float2half_rn(W2[t - 32768]);
}

// ---------------------------------------------------------------------------
// k1 (R14 verbatim): h = relu(W1@x+b1); q = relu(Wp@h+bp)
//     h -> g_cat, q -> g_q. 512 threads, 2 CTAs/SM; weights cp.async at entry.
// smem: [xb 512][W1 34816][Wp 34816][B 34816] = 104960
// ---------------------------------------------------------------------------
__global__ __launch_bounds__(512, 2)
void k1(const float* __restrict__ x, const float* __restrict__ b1v,
        const float* __restrict__ bpv)
{
    extern __shared__ unsigned char sm[];
    const uint32_t sbu = s2u(sm);
    int* xb = (int*)sm;
    __half* Bf = (__half*)(sm + 512 + 2*34816);
    __half* Qh = (__half*)(sm + 512);     // overlay W1 plane after GEMM1
    const uint32_t aW1 = sbu + 512, aWp = aW1 + 34816, aB = aWp + 34816;

    const int tid = threadIdx.x, lane = tid & 31, wid = tid >> 5;
    const int r = lane >> 2, c = (lane & 3) * 2;
    const int m0 = (wid >> 2) * 32, n0 = (wid & 3) * 32;
    const int col0 = blockIdx.x * 128;

    // W1 + Wp -> smem via cp.async, in flight during x transpose
    #pragma unroll
    for (int t = 0; t < 4; t++) {
        int i = tid + t * 512;            // 0..2047
        int m = i >> 4, ch = i & 15;
        uint32_t doff = (uint32_t)(m * 272 + ch * 16);   // S1*2 = 272B rows
        cp16(aW1 + doff, g_w1h + m * 128 + ch * 8);
        cp16(aWp + doff, g_wph + m * 128 + ch * 8);
    }
    CP_COMMIT();

    if (tid < 128) {
        int col = col0 + tid, b = col / Nn;
        xb[tid] = b * (Cc * Nn) + (col - b * Nn);
    }
    __syncthreads();                      // xb visible

    for (int i = tid; i < 16384; i += 512) {
        int j = i & 127, ch = i >> 7;
        Bf[j*S1 + ch] = __float2half_rn(x[xb[j] + ch * Nn]);
    }
    CP_WAIT(0);
    __syncthreads();                      // weights + Bf visible

    float acc[2][4][4];
    #pragma unroll
    for (int i = 0; i < 2; i++)
        #pragma unroll
        for (int j = 0; j < 4; j++)
            #pragma unroll
            for (int v = 0; v < 4; v++) acc[i][j][v] = 0.f;

    gemm_f16_2x4(acc, aW1, aB, m0, n0, lane);
    __syncthreads();                      // all GEMM1 reads of Bf done

    // Epilogue 1: h -> B plane in place (fp16)
    #pragma unroll
    for (int mi = 0; mi < 2; mi++) {
        int mr = m0 + mi*16 + r;
        float bias_a = b1v[mr], bias_b = b1v[mr + 8];
        #pragma unroll
        for (int ni = 0; ni < 4; ni++) {
            int nc = n0 + ni*8 + c;
            Bf[nc*S1 + mr]       = __float2half_rn(fmaxf(acc[mi][ni][0] + bias_a, 0.f));
            Bf[(nc+1)*S1 + mr]   = __float2half_rn(fmaxf(acc[mi][ni][1] + bias_a, 0.f));
            Bf[nc*S1 + mr+8]     = __float2half_rn(fmaxf(acc[mi][ni][2] + bias_b, 0.f));
            Bf[(nc+1)*S1 + mr+8] = __float2half_rn(fmaxf(acc[mi][ni][3] + bias_b, 0.f));
        }
    }
    __syncthreads();                      // h complete

    for (int i = tid; i < 2048; i += 512) {
        int j = i >> 4, v = i & 15;
        ((uint4*)(g_cat + (size_t)(col0 + j) * 128))[v] = ((const uint4*)(Bf + j*S1))[v];
    }

    #pragma unroll
    for (int i = 0; i < 2; i++)
        #pragma unroll
        for (int j = 0; j < 4; j++)
            #pragma unroll
            for (int v = 0; v < 4; v++) acc[i][j][v] = 0.f;

    gemm_f16_2x4(acc, aWp, aB, m0, n0, lane);
    // no sync: epilogue 2 writes the W1 plane, never read by GEMM2

    #pragma unroll
    for (int mi = 0; mi < 2; mi++) {
        int mr = m0 + mi*16 + r;
        float bias_a = bpv[mr], bias_b = bpv[mr + 8];
        #pragma unroll
        for (int ni = 0; ni < 4; ni++) {
            int nc = n0 + ni*8 + c;
            Qh[nc*S1 + mr]       = __float2half_rn(fmaxf(acc[mi][ni][0] + bias_a, 0.f));
            Qh[(nc+1)*S1 + mr]   = __float2half_rn(fmaxf(acc[mi][ni][1] + bias_a, 0.f));
            Qh[nc*S1 + mr+8]     = __float2half_rn(fmaxf(acc[mi][ni][2] + bias_b, 0.f));
            Qh[(nc+1)*S1 + mr+8] = __float2half_rn(fmaxf(acc[mi][ni][3] + bias_b, 0.f));
        }
    }
    __syncthreads();

    for (int i = tid; i < 2048; i += 512) {
        int j = i >> 4, v = i & 15;
        ((uint4*)(g_q + (size_t)(col0 + j) * 128))[v] = ((const uint4*)(Qh + j*S1))[v];
    }
}

// ---------------------------------------------------------------------------
// k2 (R11 structure + float2 epilogue stores): out = relu(W2 @ cat + b2).
// M=256, N=128/block. K=256 in 4 chunks of 64, double-buffered cp.async;
// chunks 2,3 B operand gathered in-kernel from g_q (fp16, hmax2).
// ---------------------------------------------------------------------------
#define K2_STAGE 55296
#define K2_B 36864

__device__ __forceinline__ void k2_load_a(uint32_t sbu, int stage, int ks, int tid) {
    const uint32_t base = sbu + stage * K2_STAGE;
    #pragma unroll
    for (int t = 0; t < 4; t++) {
        int i = tid + t * 512;           // 0..2047
        int m = i >> 3, ch = i & 7;
        cp16(base + (uint32_t)(m * SK + ch * 8) * 2, g_w2h + m * 256 + ks * 64 + ch * 8);
    }
}
__device__ __forceinline__ void k2_load_b_cat(uint32_t sbu, int stage, int ks,
                                              int col0, int tid) {
    const uint32_t base = sbu + stage * K2_STAGE + K2_B;
    #pragma unroll
    for (int t = 0; t < 2; t++) {
        int i = tid + t * 512;           // 0..1023
        int j = i >> 3, ch = i & 7;
        cp16(base + (uint32_t)(j * SK + ch * 8) * 2,
             g_cat + (size_t)(col0 + j) * 128 + ks * 64 + ch * 8);
    }
}

__device__ __forceinline__ void k2_gather(const int* __restrict__ eidx, int col0,
                                          int wid, int lane, uint2 g[8]) {
    #pragma unroll
    for (int t = 0; t < 8; t++) {
        int col = col0 + wid + 16 * t;
        int b = col / Nn;
        const __half* qb = g_q + (size_t)b * Nn * 128;
        int id = 0;
        if (lane < Kk) id = eidx[col * Kk + lane];
        __half2 m0 = __half2{__half(0.f), __half(0.f)}, m1 = m0;   // q >= 0
        #pragma unroll
        for (int k = 0; k < Kk; k++) {
            int nb = __shfl_sync(0xffffffffu, id, k);
            uint2 v = *(const uint2*)(qb + (size_t)nb * 128 + lane * 4);
            m0 = __hmax2(m0, *(__half2*)&v.x);
            m1 = __hmax2(m1, *(__half2*)&v.y);
        }
        g[t] = make_uint2(*(uint32_t*)&m0, *(uint32_t*)&m1);
    }
}

__device__ __forceinline__ void k2_store_gather(unsigned char* sm, int stage, int half,
                                                const uint2 g[8], int wid, int lane) {
    if ((lane >> 4) != half) return;
    const int kloc = (lane & 15) * 4;
    unsigned char* B = sm + stage * K2_STAGE + K2_B;
    #pragma unroll
    for (int t = 0; t < 8; t++) {
        int j = wid + 16 * t;
        *(uint2*)(B + (j * SK + kloc) * 2) = g[t];
    }
}

__device__ __forceinline__ void k2_gemm(float acc[2][8][4], uint32_t sbu,
                                        int stage, int m0, int n0, int lane) {
    const uint32_t st = sbu + stage * K2_STAGE;
    const int rowA = lane & 15, khalf = (lane >> 4) * 8;
    #pragma unroll
    for (int kk = 0; kk < 4; kk++) {
        const int k0 = kk * 16;
        uint32_t a[2][4];
        #pragma unroll
        for (int mi = 0; mi < 2; mi++)
            ldm4(a[mi], st + (uint32_t)(((m0 + mi*16 + rowA) * SK + k0 + khalf) * 2));
        #pragma unroll
        for (int np = 0; np < 4; np++) {
            uint32_t bm[4];
            ldm4(bm, st + K2_B + (uint32_t)(((n0 + np*16 + rowA) * SK + k0 + khalf) * 2));
            uint32_t b0[2] = {bm[0], bm[2]}, b1[2] = {bm[1], bm[3]};
            #pragma unroll
            for (int mi = 0; mi < 2; mi++) {
                mma_f16(acc[mi][2*np],   a[mi], b0);
                mma_f16(acc[mi][2*np+1], a[mi], b1);
            }
        }
    }
}

__global__ __launch_bounds__(512)
void k2(const int* __restrict__ eidx, const float* __restrict__ b2v,
        float* __restrict__ out)
{
    extern __shared__ unsigned char sm[];
    const uint32_t sbu = s2u(sm);
    const int tid = threadIdx.x, lane = tid & 31, wid = tid >> 5;
    const int r = lane >> 2, c = (lane & 3) * 2;
    const int m0 = (wid >> 1) * 32, n0 = (wid & 1) * 64;
    const int col0 = blockIdx.x * 128;

    // Prefetch chunks 0,1 (A = W2 slices; B = h from g_cat)
    k2_load_a(sbu, 0, 0, tid); k2_load_b_cat(sbu, 0, 0, col0, tid); CP_COMMIT(); // G0
    k2_load_a(sbu, 1, 1, tid); k2_load_b_cat(sbu, 1, 1, col0, tid); CP_COMMIT(); // G1

    // Gather chunks 2,3 into registers (overlaps G0/G1 arrival)
    uint2 g[8];
    k2_gather(eidx, col0, wid, lane, g);

    float acc[2][8][4];
    #pragma unroll
    for (int i = 0; i < 2; i++)
        #pragma unroll
        for (int j = 0; j < 8; j++)
            #pragma unroll
            for (int v = 0; v < 4; v++) acc[i][j][v] = 0.f;

    CP_WAIT(1); __syncthreads();           // G0 done
    k2_gemm(acc, sbu, 0, m0, n0, lane);    // chunk 0
    __syncthreads();                       // stage0 B free

    k2_store_gather(sm, 0, 0, g, wid, lane);   // chunk2 -> B(st0)
    k2_load_a(sbu, 0, 2, tid); CP_COMMIT();    // G2 (A only)
    CP_WAIT(1); __syncthreads();           // G1 done
    k2_gemm(acc, sbu, 1, m0, n0, lane);    // chunk 1
    __syncthreads();                       // stage1 B free

    k2_store_gather(sm, 1, 1, g, wid, lane);   // chunk3 -> B(st1)
    k2_load_a(sbu, 1, 3, tid); CP_COMMIT();    // G3
    CP_WAIT(1); __syncthreads();           // G2 done (+ STS visible)
    k2_gemm(acc, sbu, 0, m0, n0, lane);    // chunk 2
    __syncthreads();
    CP_WAIT(0); __syncthreads();           // G3 done
    k2_gemm(acc, sbu, 1, m0, n0, lane);    // chunk 3

    // Epilogue: bias + relu + float2 stores (full 32B sectors).
    // colA even, colB = colA+1 same batch except at n = Nn-1 (rare) -> scalar.
    #pragma unroll
    for (int mi = 0; mi < 2; mi++) {
        int mr = m0 + mi*16 + r;
        float bias_a = b2v[mr], bias_b = b2v[mr + 8];
        #pragma unroll
        for (int ni = 0; ni < 8; ni++) {
            int nc = n0 + ni*8 + c;
            int colA = col0 + nc, colB = colA + 1;
            int ba = colA / Nn, bb = colB / Nn;
            float v0 = fmaxf(acc[mi][ni][0] + bias_a, 0.f);
            float v1 = fmaxf(acc[mi][ni][1] + bias_a, 0.f);
            float v2 = fmaxf(acc[mi][ni][2] + bias_b, 0.f);
            float v3 = fmaxf(acc[mi][ni][3] + bias_b, 0.f);
            size_t obA = (size_t)ba * CO * Nn + (colA - ba * Nn);
            if (ba == bb) {
                *(float2*)(out + obA + (size_t)mr * Nn)     = make_float2(v0, v1);
                *(float2*)(out + obA + (size_t)(mr+8) * Nn) = make_float2(v2, v3);
            } else {
                size_t obB = (size_t)bb * CO * Nn + (colB - bb * Nn);
                out[obA + (size_t)mr * Nn]     = v0;
                out[obB + (size_t)mr * Nn]     = v1;
                out[obA + (size_t)(mr+8) * Nn] = v2;
                out[obB + (size_t)(mr+8) * Nn] = v3;
            }
        }
    }
}

// ---------------------------------------------------------------------------
extern "C" void kernel_launch(void* const* d_in, const int* in_sizes, int n_in,
                              void* d_out, int out_size)
{
    const float* x  = (const float*)d_in[0];
    const int*   ei = (const int*)  d_in[1];
    const float* W1 = (const float*)d_in[2];
    const float* b1 = (const float*)d_in[3];
    const float* Wp = (const float*)d_in[4];
    const float* bp = (const float*)d_in[5];
    const float* W2 = (const float*)d_in[6];
    const float* b2 = (const float*)d_in[7];
    float* out = (float*)d_out;

    const int s1 = 512 + 3 * 34816;   // 104960
    const int s2 = 2 * K2_STAGE;      // 110592
    cudaFuncSetAttribute(k1, cudaFuncAttributeMaxDynamicSharedMemorySize, s1);
    cudaFuncSetAttribute(k2, cudaFuncAttributeMaxDynamicSharedMemorySize, s2);

    kw<<<384, 256>>>(W1, Wp, W2);
    k1<<<NT / 128, 512, s1>>>(x, b1, bp);
    k2<<<NT / 128, 512, s2>>>(ei, b2, out);
}